// round 4
// baseline (speedup 1.0000x reference)
#include <cuda_runtime.h>
#include <math.h>

// Problem constants
#define BB 8
#define NN 2048
#define VV 256
#define HH 1024
#define MM (BB*NN)          // 16384 rows
#define CH 128              // scan chunk
#define NCH (NN/CH)         // 16 chunks per batch
#define SP 132              // padded smem row (floats): 528B, 16B-aligned, bank-skewed

// ---------------- scratch (static device memory; no runtime alloc) ----------
__device__ float  g_attn0[BB*VV];     // LayerNorm'd row 0 (attn branch)
__device__ float  g_mlp0[BB*VV];      // LayerNorm'd row 0 (mlp branch)
__device__ float  g_vbos[VV];         // wo_w @ wv_bos
__device__ float  g_dot0[BB];         // attn0 . qk_direction
__device__ float4 g_w[BB*NN];         // per-row softmax coeffs (w0, a, wz, _)
__device__ float  g_csum[BB*NCH*VV];  // per-chunk partial sums of h (rows>=1)
__device__ float  g_hidden[(size_t)MM*HH]; // relu(x @ w1^T), 64 MiB

// ---------------- kernel 1: LayerNorm of row 0 (both branches) + dot0 -------
__global__ void prep_ln_kernel(const float* __restrict__ h,
                               const float* __restrict__ lag, const float* __restrict__ lab,
                               const float* __restrict__ lmg, const float* __restrict__ lmb,
                               const float* __restrict__ qdir) {
    const int b = blockIdx.x, v = threadIdx.x;
    __shared__ float red[VV];
    const float x = h[(size_t)b*NN*VV + v];   // row 0 of batch b

    red[v] = x; __syncthreads();
    #pragma unroll
    for (int s = 128; s > 0; s >>= 1) { if (v < s) red[v] += red[v+s]; __syncthreads(); }
    const float mean = red[0] * (1.0f/VV);
    __syncthreads();

    const float dx = x - mean;
    red[v] = dx*dx; __syncthreads();
    #pragma unroll
    for (int s = 128; s > 0; s >>= 1) { if (v < s) red[v] += red[v+s]; __syncthreads(); }
    const float var = red[0] * (1.0f/VV);
    __syncthreads();

    const float nrm = dx / sqrtf(var + 1e-5f);
    const float a0 = nrm * lag[v] + lab[v];
    g_attn0[b*VV + v] = a0;
    g_mlp0[b*VV + v]  = nrm * lmg[v] + lmb[v];

    red[v] = a0 * qdir[v]; __syncthreads();
    #pragma unroll
    for (int s = 128; s > 0; s >>= 1) { if (v < s) red[v] += red[v+s]; __syncthreads(); }
    if (v == 0) g_dot0[b] = red[0];
}

// ---------------- kernel 2: v_bos = wo_w @ wv_bos ---------------------------
__global__ void prep_vbos_kernel(const float* __restrict__ wow,
                                 const float* __restrict__ wvb) {
    __shared__ float s[VV];
    const int i = threadIdx.x;
    s[i] = wvb[i]; __syncthreads();
    float acc = 0.f;
    #pragma unroll 8
    for (int j = 0; j < VV; ++j) acc += wow[(size_t)i*VV + j] * s[j];
    g_vbos[i] = acc;
}

// ---------------- kernel 3: per-row logits -> softmax coefficients ----------
// Row r (r>=1) of the masked softmax has entries: col0 at c=0, d at c=r-1,
// zero logits at the other (r-1) causal columns, -1e9 above diagonal (exp->0).
// attn_out[r] = w0*v_bos + wv*(a*h[r-1] + wz*cum[r]), cum[r]=sum_{1..r} h.
__global__ void dots_kernel(const float* __restrict__ h,
                            const float* __restrict__ qkb,
                            const float* __restrict__ qkp) {
    const int warp = threadIdx.x >> 5, lane = threadIdx.x & 31;
    const int idx = blockIdx.x * 8 + warp;            // 0..MM-1
    const int b = idx >> 11, r = idx & (NN-1);
    const float* row = (r == 0) ? (g_attn0 + b*VV) : (h + (size_t)idx*VV);

    float db = 0.f, dp = 0.f;
    #pragma unroll
    for (int i = 0; i < 8; ++i) {
        const int c = lane + 32*i;
        const float x = row[c];
        db += x * qkb[c];
        dp += x * qkp[c];
    }
    #pragma unroll
    for (int o = 16; o > 0; o >>= 1) {
        db += __shfl_xor_sync(0xffffffffu, db, o);
        dp += __shfl_xor_sync(0xffffffffu, dp, o);
    }
    if (lane == 0) {
        float4 w;
        if (r == 0) {
            w = make_float4(1.f, 0.f, 0.f, 0.f);
        } else {
            const float col0 = db * g_dot0[b];
            const float d = dp;
            if (r == 1) {                 // row 1: col 0 gets col0+d, col 1 zero-logit
                const float l = col0 + d;
                const float m = fmaxf(l, 0.f);
                const float e1 = expf(l - m), ez = expf(-m);
                const float iZ = 1.f / (e1 + ez);
                w = make_float4(e1*iZ, 0.f, ez*iZ, 0.f);
            } else {
                const float m = fmaxf(fmaxf(col0, d), 0.f);
                const float e0 = expf(col0 - m), ed = expf(d - m), ez = expf(-m);
                const float iZ = 1.f / (e0 + ed + (float)(r-1)*ez);
                // out = e0/Z*vbos + ed/Z*wv*h[r-1] + ez/Z*wv*(cum - h[r-1])
                w = make_float4(e0*iZ, (ed - ez)*iZ, ez*iZ, 0.f);
            }
        }
        g_w[idx] = w;
    }
}

// ---------------- kernel 4: chunk partial sums over rows (excluding row 0) --
__global__ void csum_kernel(const float* __restrict__ h) {
    const int blk = blockIdx.x;
    const int b = blk / NCH, j = blk % NCH, v = threadIdx.x;
    const int r0 = j*CH;
    const int rs = (j == 0) ? 1 : r0;
    const float* hb = h + (size_t)b*NN*VV;
    float s = 0.f;
    for (int r = rs; r < r0 + CH; ++r) s += hb[(size_t)r*VV + v];
    g_csum[(size_t)blk*VV + v] = s;
}

// ---------------- kernel 5: scan within chunk + attention output ------------
__global__ void attn_kernel(const float* __restrict__ h,
                            const float* __restrict__ wv,
                            float* __restrict__ out) {
    const int blk = blockIdx.x;
    const int b = blk / NCH, j = blk % NCH, v = threadIdx.x;
    float cum = 0.f;
    for (int jj = 0; jj < j; ++jj) cum += g_csum[((size_t)b*NCH + jj)*VV + v];

    const float vb = g_vbos[v];
    const float wvv = wv[v];
    const int r0 = j*CH;
    const float* hb = h + (size_t)b*NN*VV;
    float* ob = out + (size_t)b*NN*VV;

    float prev = (r0 > 0) ? hb[(size_t)(r0-1)*VV + v] : 0.f;
    for (int r = r0; r < r0 + CH; ++r) {
        const float cur = hb[(size_t)r*VV + v];
        if (r > 0) cum += cur;                    // cum[r] = sum_{1..r} h
        const float4 w = g_w[b*NN + r];           // broadcast load
        ob[(size_t)r*VV + v] = w.x*vb + wvv*(w.y*prev + w.z*cum);
        prev = cur;
    }
}

// ---------------- kernel 6: hidden = relu(X @ w1^T)  [16384x256 @ 256x1024] -
// X row m: batch row-0 rows replaced by g_mlp0 (mlp-branch LayerNorm).
// Double-buffered smem, padded rows for bank-conflict-free fragment loads.
__global__ void __launch_bounds__(256) gemm1_kernel(const float* __restrict__ h,
                                                    const float* __restrict__ w1) {
    __shared__ float As[2][16][SP];
    __shared__ float Bs[2][16][SP];
    const int tid = threadIdx.x;
    const int tx = tid & 15, ty = tid >> 4;
    const int m0 = blockIdx.y * 128, n0 = blockIdx.x * 128;

    // per-thread global source pointers (2 float4 loads per tile for A and B)
    const float* aptr[2];
    const float* bptr[2];
    int rowi[2], kqi[2];
    #pragma unroll
    for (int l = 0; l < 2; ++l) {
        const int f4 = tid + l*256;
        rowi[l] = f4 >> 2;
        kqi[l]  = (f4 & 3) << 2;
        const int m = m0 + rowi[l];
        aptr[l] = (((m & (NN-1)) == 0) ? (g_mlp0 + (m >> 11)*VV)
                                       : (h + (size_t)m*VV)) + kqi[l];
        bptr[l] = w1 + (size_t)(n0 + rowi[l])*VV + kqi[l];
    }

    float4 ar[2], br[2];
    #pragma unroll
    for (int l = 0; l < 2; ++l) { ar[l] = *(const float4*)aptr[l]; br[l] = *(const float4*)bptr[l]; }
    #pragma unroll
    for (int l = 0; l < 2; ++l) {
        As[0][kqi[l]+0][rowi[l]]=ar[l].x; As[0][kqi[l]+1][rowi[l]]=ar[l].y;
        As[0][kqi[l]+2][rowi[l]]=ar[l].z; As[0][kqi[l]+3][rowi[l]]=ar[l].w;
        Bs[0][kqi[l]+0][rowi[l]]=br[l].x; Bs[0][kqi[l]+1][rowi[l]]=br[l].y;
        Bs[0][kqi[l]+2][rowi[l]]=br[l].z; Bs[0][kqi[l]+3][rowi[l]]=br[l].w;
    }
    __syncthreads();

    float acc[8][8] = {};
    const int NT = VV/16;
    for (int t = 0; t < NT; ++t) {
        const int cur = t & 1;
        if (t+1 < NT) {
            #pragma unroll
            for (int l = 0; l < 2; ++l) {
                ar[l] = *(const float4*)(aptr[l] + (t+1)*16);
                br[l] = *(const float4*)(bptr[l] + (t+1)*16);
            }
        }
        #pragma unroll
        for (int k = 0; k < 16; ++k) {
            float a[8], bv[8];
            *(float4*)(a)    = *(const float4*)&As[cur][k][ty*8];
            *(float4*)(a+4)  = *(const float4*)&As[cur][k][ty*8+4];
            *(float4*)(bv)   = *(const float4*)&Bs[cur][k][tx*8];
            *(float4*)(bv+4) = *(const float4*)&Bs[cur][k][tx*8+4];
            #pragma unroll
            for (int i = 0; i < 8; ++i)
                #pragma unroll
                for (int j = 0; j < 8; ++j) acc[i][j] += a[i]*bv[j];
        }
        if (t+1 < NT) {
            const int nxt = cur ^ 1;
            #pragma unroll
            for (int l = 0; l < 2; ++l) {
                As[nxt][kqi[l]+0][rowi[l]]=ar[l].x; As[nxt][kqi[l]+1][rowi[l]]=ar[l].y;
                As[nxt][kqi[l]+2][rowi[l]]=ar[l].z; As[nxt][kqi[l]+3][rowi[l]]=ar[l].w;
                Bs[nxt][kqi[l]+0][rowi[l]]=br[l].x; Bs[nxt][kqi[l]+1][rowi[l]]=br[l].y;
                Bs[nxt][kqi[l]+2][rowi[l]]=br[l].z; Bs[nxt][kqi[l]+3][rowi[l]]=br[l].w;
            }
        }
        __syncthreads();
    }
    #pragma unroll
    for (int i = 0; i < 8; ++i) {
        float* hp = g_hidden + (size_t)(m0 + ty*8 + i)*HH + n0 + tx*8;
        const float4 o0 = make_float4(fmaxf(acc[i][0],0.f), fmaxf(acc[i][1],0.f),
                                      fmaxf(acc[i][2],0.f), fmaxf(acc[i][3],0.f));
        const float4 o1 = make_float4(fmaxf(acc[i][4],0.f), fmaxf(acc[i][5],0.f),
                                      fmaxf(acc[i][6],0.f), fmaxf(acc[i][7],0.f));
        *(float4*)hp = o0; *(float4*)(hp+4) = o1;
    }
}

// ---------------- kernel 7: out += hidden @ w2^T  [16384x1024 @ 1024x256] ---
__global__ void __launch_bounds__(256) gemm2_kernel(const float* __restrict__ w2,
                                                    float* __restrict__ out) {
    __shared__ float As[2][16][SP];
    __shared__ float Bs[2][16][SP];
    const int tid = threadIdx.x;
    const int tx = tid & 15, ty = tid >> 4;
    const int m0 = blockIdx.y * 128, n0 = blockIdx.x * 128;

    const float* aptr[2];
    const float* bptr[2];
    int rowi[2], kqi[2];
    #pragma unroll
    for (int l = 0; l < 2; ++l) {
        const int f4 = tid + l*256;
        rowi[l] = f4 >> 2;
        kqi[l]  = (f4 & 3) << 2;
        aptr[l] = g_hidden + (size_t)(m0 + rowi[l])*HH + kqi[l];
        bptr[l] = w2 + (size_t)(n0 + rowi[l])*HH + kqi[l];
    }

    float4 ar[2], br[2];
    #pragma unroll
    for (int l = 0; l < 2; ++l) { ar[l] = *(const float4*)aptr[l]; br[l] = *(const float4*)bptr[l]; }
    #pragma unroll
    for (int l = 0; l < 2; ++l) {
        As[0][kqi[l]+0][rowi[l]]=ar[l].x; As[0][kqi[l]+1][rowi[l]]=ar[l].y;
        As[0][kqi[l]+2][rowi[l]]=ar[l].z; As[0][kqi[l]+3][rowi[l]]=ar[l].w;
        Bs[0][kqi[l]+0][rowi[l]]=br[l].x; Bs[0][kqi[l]+1][rowi[l]]=br[l].y;
        Bs[0][kqi[l]+2][rowi[l]]=br[l].z; Bs[0][kqi[l]+3][rowi[l]]=br[l].w;
    }
    __syncthreads();

    float acc[8][8] = {};
    const int NT = HH/16;
    for (int t = 0; t < NT; ++t) {
        const int cur = t & 1;
        if (t+1 < NT) {
            #pragma unroll
            for (int l = 0; l < 2; ++l) {
                ar[l] = *(const float4*)(aptr[l] + (t+1)*16);
                br[l] = *(const float4*)(bptr[l] + (t+1)*16);
            }
        }
        #pragma unroll
        for (int k = 0; k < 16; ++k) {
            float a[8], bv[8];
            *(float4*)(a)    = *(const float4*)&As[cur][k][ty*8];
            *(float4*)(a+4)  = *(const float4*)&As[cur][k][ty*8+4];
            *(float4*)(bv)   = *(const float4*)&Bs[cur][k][tx*8];
            *(float4*)(bv+4) = *(const float4*)&Bs[cur][k][tx*8+4];
            #pragma unroll
            for (int i = 0; i < 8; ++i)
                #pragma unroll
                for (int j = 0; j < 8; ++j) acc[i][j] += a[i]*bv[j];
        }
        if (t+1 < NT) {
            const int nxt = cur ^ 1;
            #pragma unroll
            for (int l = 0; l < 2; ++l) {
                As[nxt][kqi[l]+0][rowi[l]]=ar[l].x; As[nxt][kqi[l]+1][rowi[l]]=ar[l].y;
                As[nxt][kqi[l]+2][rowi[l]]=ar[l].z; As[nxt][kqi[l]+3][rowi[l]]=ar[l].w;
                Bs[nxt][kqi[l]+0][rowi[l]]=br[l].x; Bs[nxt][kqi[l]+1][rowi[l]]=br[l].y;
                Bs[nxt][kqi[l]+2][rowi[l]]=br[l].z; Bs[nxt][kqi[l]+3][rowi[l]]=br[l].w;
            }
        }
        __syncthreads();
    }
    #pragma unroll
    for (int i = 0; i < 8; ++i) {
        float* op = out + (size_t)(m0 + ty*8 + i)*VV + n0 + tx*8;
        float4 c0 = *(float4*)op;
        float4 c1 = *(float4*)(op+4);
        c0.x += acc[i][0]; c0.y += acc[i][1]; c0.z += acc[i][2]; c0.w += acc[i][3];
        c1.x += acc[i][4]; c1.y += acc[i][5]; c1.z += acc[i][6]; c1.w += acc[i][7];
        *(float4*)op = c0; *(float4*)(op+4) = c1;
    }
}

// ---------------- launch ----------------------------------------------------
extern "C" void kernel_launch(void* const* d_in, const int* in_sizes, int n_in,
                              void* d_out, int out_size) {
    const float* h   = (const float*)d_in[0];
    // d_in[1] mask_one, d_in[2] mask_zero: unused (mask handled analytically)
    const float* lag = (const float*)d_in[3];
    const float* lab = (const float*)d_in[4];
    const float* lmg = (const float*)d_in[5];
    const float* lmb = (const float*)d_in[6];
    const float* wv  = (const float*)d_in[7];
    const float* wvb = (const float*)d_in[8];
    const float* wow = (const float*)d_in[9];
    const float* qkb = (const float*)d_in[10];
    const float* qkp = (const float*)d_in[11];
    const float* qkd = (const float*)d_in[12];
    const float* w1  = (const float*)d_in[13];
    const float* w2  = (const float*)d_in[14];
    float* out = (float*)d_out;

    prep_ln_kernel<<<BB, 256>>>(h, lag, lab, lmg, lmb, qkd);
    prep_vbos_kernel<<<1, 256>>>(wow, wvb);
    dots_kernel<<<MM/8, 256>>>(h, qkb, qkp);
    csum_kernel<<<BB*NCH, 256>>>(h);
    attn_kernel<<<BB*NCH, 256>>>(h, wv, out);
    gemm1_kernel<<<dim3(HH/128, MM/128), 256>>>(h, w1);
    gemm2_kernel<<<dim3(VV/128, MM/128), 256>>>(w2, out);
}

// round 6
// speedup vs baseline: 3.4266x; 3.4266x over previous
#include <cuda_runtime.h>
#include <cuda_fp16.h>
#include <math.h>
#include <stdint.h>

// Problem constants
#define BB 8
#define NN 2048
#define VV 256
#define HH 1024
#define MM (BB*NN)          // 16384 rows
#define CH 128              // scan chunk
#define NCH (NN/CH)         // 16 chunks per batch

// ---------------- scratch (static device memory; no runtime alloc) ----------
__device__ float  g_attn0[BB*VV];
__device__ float  g_mlp0[BB*VV];
__device__ float  g_vbos[VV];
__device__ float  g_dot0[BB];
__device__ float4 g_w[BB*NN];
__device__ float  g_csum[BB*NCH*VV];
// fp16 buffers (uint4 arrays for 16B alignment)
__device__ uint4  g_xh4 [(size_t)MM*VV/8];   // X  fp16 [16384][256]   8 MB
__device__ uint4  g_w1h4[(size_t)HH*VV/8];   // W1 fp16 [1024][256]
__device__ uint4  g_hid4[(size_t)MM*HH/8];   // hidden fp16 [16384][1024] 32 MB
__device__ uint4  g_w2h4[(size_t)VV*HH/8];   // W2 fp16 [256][1024]

// ======================= PTX helpers (sm_80-era, base-target safe) ==========
__device__ __forceinline__ uint32_t smem_u32(const void* p) {
    return (uint32_t)__cvta_generic_to_shared(p);
}
__device__ __forceinline__ void cpasync16(uint32_t dst, const void* src) {
    asm volatile("cp.async.cg.shared.global [%0], [%1], 16;\n" :: "r"(dst), "l"(src));
}
#define CP_COMMIT() asm volatile("cp.async.commit_group;\n" ::: "memory")
#define CP_WAIT1()  asm volatile("cp.async.wait_group 1;\n" ::: "memory")
#define CP_WAIT0()  asm volatile("cp.async.wait_group 0;\n" ::: "memory")
#define LDSM4(r, addr) \
    asm volatile("ldmatrix.sync.aligned.m8n8.x4.shared.b16 {%0,%1,%2,%3}, [%4];" \
        : "=r"((r)[0]), "=r"((r)[1]), "=r"((r)[2]), "=r"((r)[3]) : "r"(addr))
#define MMA16816(c, a, b0, b1) \
    asm volatile("mma.sync.aligned.m16n8k16.row.col.f32.f16.f16.f32 " \
        "{%0,%1,%2,%3},{%4,%5,%6,%7},{%8,%9},{%0,%1,%2,%3};" \
        : "+f"((c)[0]), "+f"((c)[1]), "+f"((c)[2]), "+f"((c)[3]) \
        : "r"((a)[0]), "r"((a)[1]), "r"((a)[2]), "r"((a)[3]), "r"(b0), "r"(b1))

// ---------------- kernel 1: LayerNorm of row 0 (both branches) + dot0 -------
__global__ void prep_ln_kernel(const float* __restrict__ h,
                               const float* __restrict__ lag, const float* __restrict__ lab,
                               const float* __restrict__ lmg, const float* __restrict__ lmb,
                               const float* __restrict__ qdir) {
    const int b = blockIdx.x, v = threadIdx.x;
    __shared__ float red[VV];
    const float x = h[(size_t)b*NN*VV + v];

    red[v] = x; __syncthreads();
    #pragma unroll
    for (int s = 128; s > 0; s >>= 1) { if (v < s) red[v] += red[v+s]; __syncthreads(); }
    const float mean = red[0] * (1.0f/VV);
    __syncthreads();

    const float dx = x - mean;
    red[v] = dx*dx; __syncthreads();
    #pragma unroll
    for (int s = 128; s > 0; s >>= 1) { if (v < s) red[v] += red[v+s]; __syncthreads(); }
    const float var = red[0] * (1.0f/VV);
    __syncthreads();

    const float nrm = dx / sqrtf(var + 1e-5f);
    const float a0 = nrm * lag[v] + lab[v];
    g_attn0[b*VV + v] = a0;
    g_mlp0[b*VV + v]  = nrm * lmg[v] + lmb[v];

    red[v] = a0 * qdir[v]; __syncthreads();
    #pragma unroll
    for (int s = 128; s > 0; s >>= 1) { if (v < s) red[v] += red[v+s]; __syncthreads(); }
    if (v == 0) g_dot0[b] = red[0];
}

// ---------------- kernel 2: v_bos = wo_w @ wv_bos ---------------------------
__global__ void prep_vbos_kernel(const float* __restrict__ wow,
                                 const float* __restrict__ wvb) {
    __shared__ float s[VV];
    const int i = threadIdx.x;
    s[i] = wvb[i]; __syncthreads();
    float acc = 0.f;
    #pragma unroll 8
    for (int j = 0; j < VV; ++j) acc += wow[(size_t)i*VV + j] * s[j];
    g_vbos[i] = acc;
}

// ---------------- kernel 3: per-row logits -> softmax coefficients ----------
__global__ void dots_kernel(const float* __restrict__ h,
                            const float* __restrict__ qkb,
                            const float* __restrict__ qkp) {
    const int warp = threadIdx.x >> 5, lane = threadIdx.x & 31;
    const int idx = blockIdx.x * 8 + warp;
    const int b = idx >> 11, r = idx & (NN-1);
    const float* row = (r == 0) ? (g_attn0 + b*VV) : (h + (size_t)idx*VV);

    float db = 0.f, dp = 0.f;
    #pragma unroll
    for (int i = 0; i < 8; ++i) {
        const int c = lane + 32*i;
        const float x = row[c];
        db += x * qkb[c];
        dp += x * qkp[c];
    }
    #pragma unroll
    for (int o = 16; o > 0; o >>= 1) {
        db += __shfl_xor_sync(0xffffffffu, db, o);
        dp += __shfl_xor_sync(0xffffffffu, dp, o);
    }
    if (lane == 0) {
        float4 w;
        if (r == 0) {
            w = make_float4(1.f, 0.f, 0.f, 0.f);
        } else {
            const float col0 = db * g_dot0[b];
            const float d = dp;
            if (r == 1) {
                const float l = col0 + d;
                const float m = fmaxf(l, 0.f);
                const float e1 = expf(l - m), ez = expf(-m);
                const float iZ = 1.f / (e1 + ez);
                w = make_float4(e1*iZ, 0.f, ez*iZ, 0.f);
            } else {
                const float m = fmaxf(fmaxf(col0, d), 0.f);
                const float e0 = expf(col0 - m), ed = expf(d - m), ez = expf(-m);
                const float iZ = 1.f / (e0 + ed + (float)(r-1)*ez);
                w = make_float4(e0*iZ, (ed - ez)*iZ, ez*iZ, 0.f);
            }
        }
        g_w[idx] = w;
    }
}

// ---------------- kernel 4: chunk partial sums over rows (excluding row 0) --
__global__ void csum_kernel(const float* __restrict__ h) {
    const int blk = blockIdx.x;
    const int b = blk / NCH, j = blk % NCH, v = threadIdx.x;
    const int r0 = j*CH;
    const int rs = (j == 0) ? 1 : r0;
    const float* hb = h + (size_t)b*NN*VV;
    float s = 0.f;
    for (int r = rs; r < r0 + CH; ++r) s += hb[(size_t)r*VV + v];
    g_csum[(size_t)blk*VV + v] = s;
}

// ---------------- kernel 5: scan within chunk + attention output ------------
__global__ void attn_kernel(const float* __restrict__ h,
                            const float* __restrict__ wv,
                            float* __restrict__ out) {
    const int blk = blockIdx.x;
    const int b = blk / NCH, j = blk % NCH, v = threadIdx.x;
    float cum = 0.f;
    for (int jj = 0; jj < j; ++jj) cum += g_csum[((size_t)b*NCH + jj)*VV + v];

    const float vb = g_vbos[v];
    const float wvv = wv[v];
    const int r0 = j*CH;
    const float* hb = h + (size_t)b*NN*VV;
    float* ob = out + (size_t)b*NN*VV;

    float prev = (r0 > 0) ? hb[(size_t)(r0-1)*VV + v] : 0.f;
    for (int r = r0; r < r0 + CH; ++r) {
        const float cur = hb[(size_t)r*VV + v];
        if (r > 0) cum += cur;
        const float4 w = g_w[b*NN + r];
        ob[(size_t)r*VV + v] = w.x*vb + wvv*(w.y*prev + w.z*cum);
        prev = cur;
    }
}

// ---------------- fp16 conversions ------------------------------------------
// X fp16 (row 0 of each batch = g_mlp0, mlp-branch LayerNorm)
__global__ void convert_x_kernel(const float* __restrict__ h) {
    const int idx = blockIdx.x*256 + threadIdx.x;   // MM*VV/4 threads
    const int m = idx >> 6;
    const int q = (idx & 63) << 2;
    const float* src = ((m & (NN-1)) == 0) ? (g_mlp0 + (m >> 11)*VV)
                                           : (h + (size_t)m*VV);
    const float4 x = *(const float4*)(src + q);
    __half2* d = (__half2*)((__half*)g_xh4 + (size_t)m*VV + q);
    d[0] = __floats2half2_rn(x.x, x.y);
    d[1] = __floats2half2_rn(x.z, x.w);
}
__global__ void convert_w1_kernel(const float* __restrict__ w1) {
    const int idx = blockIdx.x*256 + threadIdx.x;   // HH*VV/4 threads
    const int n = idx >> 6;
    const int q = (idx & 63) << 2;
    const float4 x = *(const float4*)(w1 + (size_t)n*VV + q);
    __half2* d = (__half2*)((__half*)g_w1h4 + (size_t)n*VV + q);
    d[0] = __floats2half2_rn(x.x, x.y);
    d[1] = __floats2half2_rn(x.z, x.w);
}
__global__ void convert_w2_kernel(const float* __restrict__ w2) {
    const int idx = blockIdx.x*256 + threadIdx.x;   // VV*HH/4 threads
    const int n = idx >> 8;
    const int q = (idx & 255) << 2;
    const float4 x = *(const float4*)(w2 + (size_t)n*HH + q);
    __half2* d = (__half2*)((__half*)g_w2h4 + (size_t)n*HH + q);
    d[0] = __floats2half2_rn(x.x, x.y);
    d[1] = __floats2half2_rn(x.z, x.w);
}

// ============ HMMA GEMM (sm80-style mma.sync, fp16 in / fp32 accum) =========
// C[M,N] = A[M,K] @ B[N,K]^T. Block 128x128, 8 warps in 4(m)x2(n),
// warp tile 32x64 (2 m-frags x 8 n-frags of m16n8k16). BK=32, cp.async
// double buffer. smem rows padded to 80 B => (5r+s)%8 conflict-free ldmatrix.
// IS_G1: A=g_xh4, B=g_w1h4, K=256, epilogue relu->g_hid4 (fp16).
// else : A=g_hid4, B=g_w2h4, K=1024, epilogue out += acc (fp32 rmw).
#define SMA_STRIDE 80      // bytes per smem row (40 fp16)
#define TILE_BYTES 10240   // 128 rows * 80 B

template<bool IS_G1>
__global__ void __launch_bounds__(256) gemm_mma(float* __restrict__ out) {
    constexpr int KTOT = IS_G1 ? VV : HH;
    constexpr int NCHK = KTOT / 32;
    const __half* Ag = IS_G1 ? (const __half*)g_xh4 : (const __half*)g_hid4;
    const __half* Bg = IS_G1 ? (const __half*)g_w1h4 : (const __half*)g_w2h4;

    __shared__ __align__(16) char smem[4*TILE_BYTES];   // A0 A1 B0 B1
    const uint32_t sb = smem_u32(smem);
    const int tid = threadIdx.x, lane = tid & 31, w = tid >> 5;
    const int wm = w >> 1, wn = w & 1;
    const int n0 = blockIdx.x * 128, m0 = blockIdx.y * 128;

    const __half* Arow = Ag + (size_t)m0 * KTOT;
    const __half* Brow = Bg + (size_t)n0 * KTOT;
    const int lr = tid >> 2, ls = tid & 3;              // load row/seg (+256: rows 64..127)

    // ---- prefetch chunk 0 into buffer 0
    {
        const uint32_t ab = sb, bb = sb + 2*TILE_BYTES;
        #pragma unroll
        for (int i = 0; i < 2; ++i) {
            const int r = lr + i*64;
            cpasync16(ab + r*SMA_STRIDE + ls*16, Arow + (size_t)r*KTOT + ls*8);
            cpasync16(bb + r*SMA_STRIDE + ls*16, Brow + (size_t)r*KTOT + ls*8);
        }
        CP_COMMIT();
    }

    float acc[2][8][4];
    #pragma unroll
    for (int i = 0; i < 2; ++i)
        #pragma unroll
        for (int j = 0; j < 8; ++j)
            #pragma unroll
            for (int k = 0; k < 4; ++k) acc[i][j][k] = 0.f;

    for (int c = 0; c < NCHK; ++c) {
        const int buf = c & 1;
        if (c + 1 < NCHK) {
            const uint32_t ab = sb + (buf^1)*TILE_BYTES;
            const uint32_t bb = sb + 2*TILE_BYTES + (buf^1)*TILE_BYTES;
            #pragma unroll
            for (int i = 0; i < 2; ++i) {
                const int r = lr + i*64;
                cpasync16(ab + r*SMA_STRIDE + ls*16, Arow + (size_t)r*KTOT + (c+1)*32 + ls*8);
                cpasync16(bb + r*SMA_STRIDE + ls*16, Brow + (size_t)r*KTOT + (c+1)*32 + ls*8);
            }
            CP_COMMIT();
            CP_WAIT1();
        } else {
            CP_WAIT0();
        }
        __syncthreads();

        const uint32_t ab = sb + buf*TILE_BYTES;
        const uint32_t bb = sb + 2*TILE_BYTES + buf*TILE_BYTES;
        #pragma unroll
        for (int kb = 0; kb < 2; ++kb) {                // two k16 steps
            uint32_t afr[2][4], bfr[4][4];
            #pragma unroll
            for (int mt = 0; mt < 2; ++mt) {
                const uint32_t addr = ab + (wm*32 + mt*16 + (lane & 15))*SMA_STRIDE
                                    + kb*32 + ((lane >> 4) << 4);
                LDSM4(afr[mt], addr);
            }
            #pragma unroll
            for (int nt2 = 0; nt2 < 4; ++nt2) {         // each x4 = two n8 frags
                const uint32_t addr = bb + (wn*64 + nt2*16 + (lane & 7) + ((lane >> 4) << 3))*SMA_STRIDE
                                    + kb*32 + (((lane >> 3) & 1) << 4);
                LDSM4(bfr[nt2], addr);
            }
            #pragma unroll
            for (int mt = 0; mt < 2; ++mt)
                #pragma unroll
                for (int nt = 0; nt < 8; ++nt)
                    MMA16816(acc[mt][nt], afr[mt], bfr[nt >> 1][(nt & 1)*2],
                             bfr[nt >> 1][(nt & 1)*2 + 1]);
        }
        __syncthreads();
    }

    // ---- epilogue
    const int r4 = lane >> 2, j2 = (lane & 3) << 1;
    if (IS_G1) {
        __half* H = (__half*)g_hid4;
        #pragma unroll
        for (int mt = 0; mt < 2; ++mt)
            #pragma unroll
            for (int nt = 0; nt < 8; ++nt) {
                const int m   = m0 + wm*32 + mt*16 + r4;
                const int col = n0 + wn*64 + nt*8 + j2;
                float* cc = acc[mt][nt];
                *(__half2*)(H + (size_t)m*HH + col) =
                    __floats2half2_rn(fmaxf(cc[0], 0.f), fmaxf(cc[1], 0.f));
                *(__half2*)(H + (size_t)(m+8)*HH + col) =
                    __floats2half2_rn(fmaxf(cc[2], 0.f), fmaxf(cc[3], 0.f));
            }
    } else {
        #pragma unroll
        for (int mt = 0; mt < 2; ++mt)
            #pragma unroll
            for (int nt = 0; nt < 8; ++nt) {
                const int m   = m0 + wm*32 + mt*16 + r4;
                const int col = n0 + wn*64 + nt*8 + j2;
                float* cc = acc[mt][nt];
                float2* p0 = (float2*)(out + (size_t)m*VV + col);
                float2* p1 = (float2*)(out + (size_t)(m+8)*VV + col);
                float2 v0 = *p0, v1 = *p1;
                v0.x += cc[0]; v0.y += cc[1];
                v1.x += cc[2]; v1.y += cc[3];
                *p0 = v0; *p1 = v1;
            }
    }
}

// ---------------- launch ----------------------------------------------------
extern "C" void kernel_launch(void* const* d_in, const int* in_sizes, int n_in,
                              void* d_out, int out_size) {
    const float* h   = (const float*)d_in[0];
    // d_in[1] mask_one, d_in[2] mask_zero: unused (mask handled analytically)
    const float* lag = (const float*)d_in[3];
    const float* lab = (const float*)d_in[4];
    const float* lmg = (const float*)d_in[5];
    const float* lmb = (const float*)d_in[6];
    const float* wv  = (const float*)d_in[7];
    const float* wvb = (const float*)d_in[8];
    const float* wow = (const float*)d_in[9];
    const float* qkb = (const float*)d_in[10];
    const float* qkp = (const float*)d_in[11];
    const float* qkd = (const float*)d_in[12];
    const float* w1  = (const float*)d_in[13];
    const float* w2  = (const float*)d_in[14];
    float* out = (float*)d_out;

    prep_ln_kernel<<<BB, 256>>>(h, lag, lab, lmg, lmb, qkd);
    prep_vbos_kernel<<<1, 256>>>(wow, wvb);
    dots_kernel<<<MM/8, 256>>>(h, qkb, qkp);
    csum_kernel<<<BB*NCH, 256>>>(h);
    attn_kernel<<<BB*NCH, 256>>>(h, wv, out);

    convert_x_kernel<<<(MM*VV/4)/256, 256>>>(h);
    convert_w1_kernel<<<(HH*VV/4)/256, 256>>>(w1);
    convert_w2_kernel<<<(VV*HH/4)/256, 256>>>(w2);

    gemm_mma<true ><<<dim3(HH/128, MM/128), 256>>>(nullptr);  // X @ W1^T -> relu -> hidden
    gemm_mma<false><<<dim3(VV/128, MM/128), 256>>>(out);      // hidden @ W2^T += out
}

// round 9
// speedup vs baseline: 3.7577x; 1.0966x over previous
#include <cuda_runtime.h>
#include <cuda_fp16.h>
#include <math.h>
#include <stdint.h>

// Problem constants
#define BB 8
#define NN 2048
#define VV 256
#define HH 1024
#define MM (BB*NN)          // 16384 rows
#define CH2 32              // scan chunk (fine-grained)
#define NCH2 (NN/CH2)       // 64 chunks per batch

// ---------------- scratch (static device memory; no runtime alloc) ----------
__device__ float  g_attn0[BB*VV];
__device__ float  g_mlp0[BB*VV];
__device__ float  g_vbos[VV];
__device__ float  g_dot0[BB];
__device__ float4 g_w[BB*NN];
__device__ float  g_csum[BB*NCH2*VV];        // 32-row partial sums (512 KB)
// fp16 buffers (uint4 arrays for 16B alignment)
__device__ uint4  g_xh4 [(size_t)MM*VV/8];   // X  fp16 [16384][256]   8 MB
__device__ uint4  g_w1h4[(size_t)HH*VV/8];   // W1 fp16 [1024][256]
__device__ uint4  g_hid4[(size_t)MM*HH/8];   // hidden fp16 [16384][1024] 32 MB
__device__ uint4  g_w2h4[(size_t)VV*HH/8];   // W2 fp16 [256][1024]

// ======================= PTX helpers (sm_80-era, base-target safe) ==========
__device__ __forceinline__ uint32_t smem_u32(const void* p) {
    return (uint32_t)__cvta_generic_to_shared(p);
}
__device__ __forceinline__ void cpasync16(uint32_t dst, const void* src) {
    asm volatile("cp.async.cg.shared.global [%0], [%1], 16;\n" :: "r"(dst), "l"(src));
}
#define CP_COMMIT() asm volatile("cp.async.commit_group;\n" ::: "memory")
#define CP_WAIT1()  asm volatile("cp.async.wait_group 1;\n" ::: "memory")
#define CP_WAIT0()  asm volatile("cp.async.wait_group 0;\n" ::: "memory")
#define LDSM4(r, addr) \
    asm volatile("ldmatrix.sync.aligned.m8n8.x4.shared.b16 {%0,%1,%2,%3}, [%4];" \
        : "=r"((r)[0]), "=r"((r)[1]), "=r"((r)[2]), "=r"((r)[3]) : "r"(addr))
#define MMA16816(c, a, b0, b1) \
    asm volatile("mma.sync.aligned.m16n8k16.row.col.f32.f16.f16.f32 " \
        "{%0,%1,%2,%3},{%4,%5,%6,%7},{%8,%9},{%0,%1,%2,%3};" \
        : "+f"((c)[0]), "+f"((c)[1]), "+f"((c)[2]), "+f"((c)[3]) \
        : "r"((a)[0]), "r"((a)[1]), "r"((a)[2]), "r"((a)[3]), "r"(b0), "r"(b1))

// ---------------- kernel 1: LayerNorm of row 0 (both branches) + dot0 -------
__global__ void prep_ln_kernel(const float* __restrict__ h,
                               const float* __restrict__ lag, const float* __restrict__ lab,
                               const float* __restrict__ lmg, const float* __restrict__ lmb,
                               const float* __restrict__ qdir) {
    const int b = blockIdx.x, v = threadIdx.x;
    __shared__ float red[VV];
    const float x = h[(size_t)b*NN*VV + v];

    red[v] = x; __syncthreads();
    #pragma unroll
    for (int s = 128; s > 0; s >>= 1) { if (v < s) red[v] += red[v+s]; __syncthreads(); }
    const float mean = red[0] * (1.0f/VV);
    __syncthreads();

    const float dx = x - mean;
    red[v] = dx*dx; __syncthreads();
    #pragma unroll
    for (int s = 128; s > 0; s >>= 1) { if (v < s) red[v] += red[v+s]; __syncthreads(); }
    const float var = red[0] * (1.0f/VV);
    __syncthreads();

    const float nrm = dx / sqrtf(var + 1e-5f);
    const float a0 = nrm * lag[v] + lab[v];
    g_attn0[b*VV + v] = a0;
    g_mlp0[b*VV + v]  = nrm * lmg[v] + lmb[v];

    red[v] = a0 * qdir[v]; __syncthreads();
    #pragma unroll
    for (int s = 128; s > 0; s >>= 1) { if (v < s) red[v] += red[v+s]; __syncthreads(); }
    if (v == 0) g_dot0[b] = red[0];
}

// ---------------- kernel 2: v_bos = wo_w @ wv_bos ---------------------------
__global__ void prep_vbos_kernel(const float* __restrict__ wow,
                                 const float* __restrict__ wvb) {
    __shared__ float s[VV];
    const int i = threadIdx.x;
    s[i] = wvb[i]; __syncthreads();
    float acc = 0.f;
    #pragma unroll 8
    for (int j = 0; j < VV; ++j) acc += wow[(size_t)i*VV + j] * s[j];
    g_vbos[i] = acc;
}

// ------- kernel 3: fused per-row logits -> coeffs  +  fp16 conversion of X --
__global__ void dots_kernel(const float* __restrict__ h,
                            const float* __restrict__ qkb,
                            const float* __restrict__ qkp) {
    const int warp = threadIdx.x >> 5, lane = threadIdx.x & 31;
    const int idx = blockIdx.x * 8 + warp;
    const int b = idx >> 11, r = idx & (NN-1);
    const float* row = (r == 0) ? (g_attn0 + b*VV) : (h + (size_t)idx*VV);
    __half* xrow = (__half*)g_xh4 + (size_t)idx*VV;

    float db = 0.f, dp = 0.f;
    #pragma unroll
    for (int i = 0; i < 8; ++i) {
        const int c = lane + 32*i;
        const float x = row[c];
        db += x * qkb[c];
        dp += x * qkp[c];
        // mlp-branch input: row 0 uses g_mlp0, others use x itself
        const float cx = (r == 0) ? g_mlp0[b*VV + c] : x;
        xrow[c] = __float2half_rn(cx);
    }
    #pragma unroll
    for (int o = 16; o > 0; o >>= 1) {
        db += __shfl_xor_sync(0xffffffffu, db, o);
        dp += __shfl_xor_sync(0xffffffffu, dp, o);
    }
    if (lane == 0) {
        float4 w;
        if (r == 0) {
            w = make_float4(1.f, 0.f, 0.f, 0.f);
        } else {
            const float col0 = db * g_dot0[b];
            const float d = dp;
            if (r == 1) {
                const float l = col0 + d;
                const float m = fmaxf(l, 0.f);
                const float e1 = expf(l - m), ez = expf(-m);
                const float iZ = 1.f / (e1 + ez);
                w = make_float4(e1*iZ, 0.f, ez*iZ, 0.f);
            } else {
                const float m = fmaxf(fmaxf(col0, d), 0.f);
                const float e0 = expf(col0 - m), ed = expf(d - m), ez = expf(-m);
                const float iZ = 1.f / (e0 + ed + (float)(r-1)*ez);
                w = make_float4(e0*iZ, (ed - ez)*iZ, ez*iZ, 0.f);
            }
        }
        g_w[idx] = w;
    }
}

// ---- kernel 4: 32-row partial sums (row 0 excluded), float4 + 4 row-groups -
__global__ void csum_kernel(const float* __restrict__ h) {
    const int blk = blockIdx.x;                 // BB*NCH2 = 512 blocks
    const int b = blk / NCH2, j = blk % NCH2;
    const int q4 = threadIdx.x & 63;            // float4 column 0..63
    const int g  = threadIdx.x >> 6;            // row group 0..3
    const int r0 = j*CH2 + g*8;
    const int rs = (j == 0 && g == 0) ? 1 : r0;
    const float* hb = h + (size_t)b*NN*VV;

    float4 s = make_float4(0.f, 0.f, 0.f, 0.f);
    for (int r = rs; r < r0 + 8; ++r) {
        const float4 x = *(const float4*)(hb + (size_t)r*VV + q4*4);
        s.x += x.x; s.y += x.y; s.z += x.z; s.w += x.w;
    }
    __shared__ float4 red[4][64];
    red[g][q4] = s;
    __syncthreads();
    if (g == 0) {
        float4 a = red[0][q4], b1 = red[1][q4], c = red[2][q4], d = red[3][q4];
        a.x += b1.x + c.x + d.x; a.y += b1.y + c.y + d.y;
        a.z += b1.z + c.z + d.z; a.w += b1.w + c.w + d.w;
        *(float4*)(g_csum + (size_t)blk*VV + q4*4) = a;
    }
}

// ---------------- kernel 5: scan within 32-row chunk + attention output -----
__global__ void attn_kernel(const float* __restrict__ h,
                            const float* __restrict__ wv,
                            float* __restrict__ out) {
    const int blk = blockIdx.x;                 // BB*NCH2 = 512 blocks
    const int b = blk / NCH2, j = blk % NCH2, v = threadIdx.x;
    float cum = 0.f;
    for (int jj = 0; jj < j; ++jj) cum += g_csum[((size_t)b*NCH2 + jj)*VV + v];

    const float vb = g_vbos[v];
    const float wvv = wv[v];
    const int r0 = j*CH2;
    const float* hb = h + (size_t)b*NN*VV;
    float* ob = out + (size_t)b*NN*VV;

    float prev = (r0 > 0) ? hb[(size_t)(r0-1)*VV + v] : 0.f;
    #pragma unroll 4
    for (int r = r0; r < r0 + CH2; ++r) {
        const float cur = hb[(size_t)r*VV + v];
        if (r > 0) cum += cur;
        const float4 w = g_w[b*NN + r];
        ob[(size_t)r*VV + v] = w.x*vb + wvv*(w.y*prev + w.z*cum);
        prev = cur;
    }
}

// ---------------- weight fp16 conversions ------------------------------------
__global__ void convert_w1_kernel(const float* __restrict__ w1) {
    const int idx = blockIdx.x*256 + threadIdx.x;   // HH*VV/4 threads
    const int n = idx >> 6;
    const int q = (idx & 63) << 2;
    const float4 x = *(const float4*)(w1 + (size_t)n*VV + q);
    __half2* d = (__half2*)((__half*)g_w1h4 + (size_t)n*VV + q);
    d[0] = __floats2half2_rn(x.x, x.y);
    d[1] = __floats2half2_rn(x.z, x.w);
}
__global__ void convert_w2_kernel(const float* __restrict__ w2) {
    const int idx = blockIdx.x*256 + threadIdx.x;   // VV*HH/4 threads
    const int n = idx >> 8;
    const int q = (idx & 255) << 2;
    const float4 x = *(const float4*)(w2 + (size_t)n*HH + q);
    __half2* d = (__half2*)((__half*)g_w2h4 + (size_t)n*HH + q);
    d[0] = __floats2half2_rn(x.x, x.y);
    d[1] = __floats2half2_rn(x.z, x.w);
}

// ============ HMMA GEMM (sm80-style mma.sync, fp16 in / fp32 accum) =========
// C[M,N] = A[M,K] @ B[N,K]^T. Block 128x128, 8 warps in 4(m)x2(n),
// warp tile 32x64. BK=32, 3-stage cp.async pipeline, ONE sync per chunk.
// smem rows padded to 80 B => (5r+s)%8 conflict-free ldmatrix.
#define SMA_STRIDE 80      // bytes per smem row (40 fp16)
#define TILE_BYTES 10240   // 128 rows * 80 B
#define NSTAGE 3
#define GEMM_SMEM (2*NSTAGE*TILE_BYTES)   // 61440 B (dynamic)

template<bool IS_G1>
__global__ void __launch_bounds__(256) gemm_mma(float* __restrict__ out) {
    constexpr int KTOT = IS_G1 ? VV : HH;
    constexpr int NCHK = KTOT / 32;
    const __half* Ag = IS_G1 ? (const __half*)g_xh4 : (const __half*)g_hid4;
    const __half* Bg = IS_G1 ? (const __half*)g_w1h4 : (const __half*)g_w2h4;

    extern __shared__ __align__(16) char smem[];   // [A0 A1 A2 | B0 B1 B2]
    const uint32_t sb = smem_u32(smem);
    const int tid = threadIdx.x, lane = tid & 31, w = tid >> 5;
    const int wm = w >> 1, wn = w & 1;
    const int n0 = blockIdx.x * 128, m0 = blockIdx.y * 128;

    const __half* Arow = Ag + (size_t)m0 * KTOT;
    const __half* Brow = Bg + (size_t)n0 * KTOT;
    const int lr = tid >> 2, ls = tid & 3;          // load row/seg

    // ---- prefetch chunks 0..NSTAGE-2
    #pragma unroll
    for (int s = 0; s < NSTAGE-1; ++s) {
        const uint32_t ab = sb + s*TILE_BYTES;
        const uint32_t bb = sb + NSTAGE*TILE_BYTES + s*TILE_BYTES;
        #pragma unroll
        for (int i = 0; i < 2; ++i) {
            const int r = lr + i*64;
            cpasync16(ab + r*SMA_STRIDE + ls*16, Arow + (size_t)r*KTOT + s*32 + ls*8);
            cpasync16(bb + r*SMA_STRIDE + ls*16, Brow + (size_t)r*KTOT + s*32 + ls*8);
        }
        CP_COMMIT();
    }

    float acc[2][8][4];
    #pragma unroll
    for (int i = 0; i < 2; ++i)
        #pragma unroll
        for (int j = 0; j < 8; ++j)
            #pragma unroll
            for (int k = 0; k < 4; ++k) acc[i][j][k] = 0.f;

    for (int c = 0; c < NCHK; ++c) {
        const int buf = c % NSTAGE;
        if (c == NCHK-1) { CP_WAIT0(); } else { CP_WAIT1(); }
        __syncthreads();
        // prefetch chunk c+NSTAGE-1 into buffer (c+NSTAGE-1)%NSTAGE = (c-1)%NSTAGE
        // (safe: sync above proves all warps finished compute(c-1))
        if (c + NSTAGE-1 < NCHK) {
            const int pb = (c + NSTAGE-1) % NSTAGE;
            const uint32_t ab = sb + pb*TILE_BYTES;
            const uint32_t bb = sb + NSTAGE*TILE_BYTES + pb*TILE_BYTES;
            #pragma unroll
            for (int i = 0; i < 2; ++i) {
                const int r = lr + i*64;
                cpasync16(ab + r*SMA_STRIDE + ls*16,
                          Arow + (size_t)r*KTOT + (c+NSTAGE-1)*32 + ls*8);
                cpasync16(bb + r*SMA_STRIDE + ls*16,
                          Brow + (size_t)r*KTOT + (c+NSTAGE-1)*32 + ls*8);
            }
            CP_COMMIT();
        }

        const uint32_t ab = sb + buf*TILE_BYTES;
        const uint32_t bb = sb + NSTAGE*TILE_BYTES + buf*TILE_BYTES;
        #pragma unroll
        for (int kb = 0; kb < 2; ++kb) {            // two k16 steps
            uint32_t afr[2][4], bfr[4][4];
            #pragma unroll
            for (int mt = 0; mt < 2; ++mt) {
                const uint32_t addr = ab + (wm*32 + mt*16 + (lane & 15))*SMA_STRIDE
                                    + kb*32 + ((lane >> 4) << 4);
                LDSM4(afr[mt], addr);
            }
            #pragma unroll
            for (int nt2 = 0; nt2 < 4; ++nt2) {     // each x4 = two n8 frags
                const uint32_t addr = bb + (wn*64 + nt2*16 + (lane & 7) + ((lane >> 4) << 3))*SMA_STRIDE
                                    + kb*32 + (((lane >> 3) & 1) << 4);
                LDSM4(bfr[nt2], addr);
            }
            #pragma unroll
            for (int mt = 0; mt < 2; ++mt)
                #pragma unroll
                for (int nt = 0; nt < 8; ++nt)
                    MMA16816(acc[mt][nt], afr[mt], bfr[nt >> 1][(nt & 1)*2],
                             bfr[nt >> 1][(nt & 1)*2 + 1]);
        }
    }

    // ---- epilogue
    const int r4 = lane >> 2, j2 = (lane & 3) << 1;
    if (IS_G1) {
        __half* H = (__half*)g_hid4;
        #pragma unroll
        for (int mt = 0; mt < 2; ++mt)
            #pragma unroll
            for (int nt = 0; nt < 8; ++nt) {
                const int m   = m0 + wm*32 + mt*16 + r4;
                const int col = n0 + wn*64 + nt*8 + j2;
                float* cc = acc[mt][nt];
                *(__half2*)(H + (size_t)m*HH + col) =
                    __floats2half2_rn(fmaxf(cc[0], 0.f), fmaxf(cc[1], 0.f));
                *(__half2*)(H + (size_t)(m+8)*HH + col) =
                    __floats2half2_rn(fmaxf(cc[2], 0.f), fmaxf(cc[3], 0.f));
            }
    } else {
        #pragma unroll
        for (int mt = 0; mt < 2; ++mt)
            #pragma unroll
            for (int nt = 0; nt < 8; ++nt) {
                const int m   = m0 + wm*32 + mt*16 + r4;
                const int col = n0 + wn*64 + nt*8 + j2;
                float* cc = acc[mt][nt];
                float2* p0 = (float2*)(out + (size_t)m*VV + col);
                float2* p1 = (float2*)(out + (size_t)(m+8)*VV + col);
                float2 v0 = *p0, v1 = *p1;
                v0.x += cc[0]; v0.y += cc[1];
                v1.x += cc[2]; v1.y += cc[3];
                *p0 = v0; *p1 = v1;
            }
    }
}

// ---------------- launch ----------------------------------------------------
extern "C" void kernel_launch(void* const* d_in, const int* in_sizes, int n_in,
                              void* d_out, int out_size) {
    const float* h   = (const float*)d_in[0];
    // d_in[1] mask_one, d_in[2] mask_zero: unused (mask handled analytically)
    const float* lag = (const float*)d_in[3];
    const float* lab = (const float*)d_in[4];
    const float* lmg = (const float*)d_in[5];
    const float* lmb = (const float*)d_in[6];
    const float* wv  = (const float*)d_in[7];
    const float* wvb = (const float*)d_in[8];
    const float* wow = (const float*)d_in[9];
    const float* qkb = (const float*)d_in[10];
    const float* qkp = (const float*)d_in[11];
    const float* qkd = (const float*)d_in[12];
    const float* w1  = (const float*)d_in[13];
    const float* w2  = (const float*)d_in[14];
    float* out = (float*)d_out;

    cudaFuncSetAttribute(gemm_mma<true >, cudaFuncAttributeMaxDynamicSharedMemorySize, GEMM_SMEM);
    cudaFuncSetAttribute(gemm_mma<false>, cudaFuncAttributeMaxDynamicSharedMemorySize, GEMM_SMEM);

    prep_ln_kernel<<<BB, 256>>>(h, lag, lab, lmg, lmb, qkd);
    prep_vbos_kernel<<<1, 256>>>(wow, wvb);
    dots_kernel<<<MM/8, 256>>>(h, qkb, qkp);          // + fp16 X conversion
    csum_kernel<<<BB*NCH2, 256>>>(h);
    attn_kernel<<<BB*NCH2, 256>>>(h, wv, out);

    convert_w1_kernel<<<(HH*VV/4)/256, 256>>>(w1);
    convert_w2_kernel<<<(VV*HH/4)/256, 256>>>(w2);

    gemm_mma<true ><<<dim3(HH/128, MM/128), 256, GEMM_SMEM>>>(nullptr);
    gemm_mma<false><<<dim3(VV/128, MM/128), 256, GEMM_SMEM>>>(out);
}